// round 1
// baseline (speedup 1.0000x reference)
#include <cuda_runtime.h>
#include <cuda_fp16.h>

#define STR 132           // padded shared row stride (floats); 132*4B = 528B, 16B-aligned rows
#define THREADS 256

// ---------------- f32x2 helpers (sm_103a packed fp32, 2x FFMA throughput) ----------------
__device__ __forceinline__ unsigned long long dup_f32x2(float a) {
    unsigned long long r;
    unsigned int ai = __float_as_uint(a);
    asm("mov.b64 %0, {%1, %1};" : "=l"(r) : "r"(ai));
    return r;
}
__device__ __forceinline__ void fma2(unsigned long long &acc, unsigned long long a, unsigned long long b) {
    asm("fma.rn.f32x2 %0, %1, %2, %0;" : "+l"(acc) : "l"(a), "l"(b));
}
__device__ __forceinline__ float2 unpack2(unsigned long long v) {
    unsigned int lo, hi;
    asm("mov.b64 {%0, %1}, %2;" : "=r"(lo), "=r"(hi) : "l"(v));
    return make_float2(__uint_as_float(lo), __uint_as_float(hi));
}

// Lloyd-Max bucketize: idx = #{ interior boundaries < v } (matches searchsorted side='left'),
// then gather centroid. sB[1..15] are the interior boundaries, sC[0..15] centroids.
__device__ __forceinline__ float quantize1(float v, const float* __restrict__ sB,
                                           const float* __restrict__ sC) {
    int idx = (v > sB[8]) ? 8 : 0;
    idx += (v > sB[idx + 4]) ? 4 : 0;
    idx += (v > sB[idx + 2]) ? 2 : 0;
    idx += (v > sB[idx + 1]) ? 1 : 0;
    return sC[idx];
}

__global__ __launch_bounds__(THREADS, 1)
void tq_kernel(const float* __restrict__ x, const float* __restrict__ Pi,
               const float* __restrict__ cen, const float* __restrict__ bnd,
               float* __restrict__ out, int n_tiles)
{
    extern __shared__ float smem[];
    float* sPi  = smem;                  // [128][STR] Pi[j][k] row-major
    float* sPiT = sPi  + 128 * STR;      // [128][STR] PiT[k][j]
    float* sX   = sPiT + 128 * STR;      // [128][STR] x tile rows; reused as values tile
    float* sRn  = sX   + 128 * STR;      // [128] 1/(norm+1e-8)
    float* sNq  = sRn  + 128;            // [128] fp16-roundtripped norm
    float* sB   = sNq  + 128;            // [16] boundaries (indices 1..15 used)
    float* sC   = sB   + 16;             // [16] centroids

    const int tid = threadIdx.x;
    const int tc  = tid & 15;            // output-column group (4 cols + 4 cols at +64)
    const int tr  = tid >> 4;            // output-row group   (4 rows + 4 rows at +64)

    // ---- stage Pi and PiT once per block ----
    #pragma unroll
    for (int it = 0; it < 16; ++it) {
        int idx = it * 256 + tid;
        int r = idx >> 5, c4 = idx & 31;
        float4 v = reinterpret_cast<const float4*>(Pi)[idx];
        *reinterpret_cast<float4*>(&sPi[r * STR + c4 * 4]) = v;
        sPiT[(c4 * 4 + 0) * STR + r] = v.x;
        sPiT[(c4 * 4 + 1) * STR + r] = v.y;
        sPiT[(c4 * 4 + 2) * STR + r] = v.z;
        sPiT[(c4 * 4 + 3) * STR + r] = v.w;
    }
    if (tid < 16) sC[tid] = cen[tid];
    if (tid < 16) sB[tid] = bnd[tid];    // sB[0] (=-1) unused by search
    __syncthreads();

    for (int tile = blockIdx.x; tile < n_tiles; tile += gridDim.x) {
        const float* gx   = x   + (size_t)tile * 128 * 128;
        float*       gout = out + (size_t)tile * 128 * 128;

        __syncthreads();  // previous tile's readers of sX are done

        // ---- stage x tile (coalesced 512B per warp per iter) ----
        #pragma unroll
        for (int it = 0; it < 16; ++it) {
            int idx = it * 256 + tid;
            int r = idx >> 5, c4 = idx & 31;
            float4 v = reinterpret_cast<const float4*>(gx)[idx];
            *reinterpret_cast<float4*>(&sX[r * STR + c4 * 4]) = v;
        }
        __syncthreads();

        // ---- per-row norms ----
        if (tid < 128) {
            const float* row = &sX[tid * STR];
            float s = 0.f;
            #pragma unroll
            for (int k = 0; k < 128; k += 4) {
                float4 v = *reinterpret_cast<const float4*>(&row[k]);
                s += v.x * v.x + v.y * v.y + v.z * v.z + v.w * v.w;
            }
            float nrm = sqrtf(s);
            sRn[tid] = 1.0f / (nrm + 1e-8f);
            sNq[tid] = __half2float(__float2half_rn(nrm));
        }
        __syncthreads();

        // ---- matmul 1: rot[r][j] = sum_k x[r][k] * Pi[j][k]  (scale by 1/norm afterwards) ----
        unsigned long long acc[8][4];
        #pragma unroll
        for (int i = 0; i < 8; ++i)
            #pragma unroll
            for (int j = 0; j < 4; ++j) acc[i][j] = 0ull;

        {
            const float* aP = sX  + (tr * 4) * STR;   // rows tr*4+{0..3}, +64..+67; col k
            const float* bP = sPiT + tc * 4;          // row k, cols tc*4+{0..3}, +64..+67
            #pragma unroll 4
            for (int k = 0; k < 128; ++k) {
                ulonglong2 b0 = *reinterpret_cast<const ulonglong2*>(bP);
                ulonglong2 b1 = *reinterpret_cast<const ulonglong2*>(bP + 64);
                #pragma unroll
                for (int i = 0; i < 8; ++i) {
                    int off = (i < 4) ? (i * STR) : ((i + 60) * STR);
                    unsigned long long ad = dup_f32x2(aP[off]);
                    fma2(acc[i][0], ad, b0.x);
                    fma2(acc[i][1], ad, b0.y);
                    fma2(acc[i][2], ad, b1.x);
                    fma2(acc[i][3], ad, b1.y);
                }
                aP += 1; bP += STR;
            }
        }

        __syncthreads();  // everyone done reading x tile before overwriting with values

        // ---- quantize (fused) and write values tile ----
        #pragma unroll
        for (int i = 0; i < 8; ++i) {
            int r = tr * 4 + ((i < 4) ? i : (i + 60));
            float rnv = sRn[r];
            float q[8];
            #pragma unroll
            for (int jp = 0; jp < 4; ++jp) {
                float2 p = unpack2(acc[i][jp]);
                q[2 * jp + 0] = quantize1(p.x * rnv, sB, sC);
                q[2 * jp + 1] = quantize1(p.y * rnv, sB, sC);
            }
            *reinterpret_cast<float4*>(&sX[r * STR + tc * 4])      = make_float4(q[0], q[1], q[2], q[3]);
            *reinterpret_cast<float4*>(&sX[r * STR + tc * 4 + 64]) = make_float4(q[4], q[5], q[6], q[7]);
        }
        __syncthreads();

        // ---- matmul 2: recon[r][k] = sum_j values[r][j] * Pi[j][k] ----
        #pragma unroll
        for (int i = 0; i < 8; ++i)
            #pragma unroll
            for (int j = 0; j < 4; ++j) acc[i][j] = 0ull;

        {
            const float* aP = sX  + (tr * 4) * STR;   // values row, col j
            const float* bP = sPi + tc * 4;           // Pi row j, cols tc*4..
            #pragma unroll 4
            for (int j = 0; j < 128; ++j) {
                ulonglong2 b0 = *reinterpret_cast<const ulonglong2*>(bP);
                ulonglong2 b1 = *reinterpret_cast<const ulonglong2*>(bP + 64);
                #pragma unroll
                for (int i = 0; i < 8; ++i) {
                    int off = (i < 4) ? (i * STR) : ((i + 60) * STR);
                    unsigned long long ad = dup_f32x2(aP[off]);
                    fma2(acc[i][0], ad, b0.x);
                    fma2(acc[i][1], ad, b0.y);
                    fma2(acc[i][2], ad, b1.x);
                    fma2(acc[i][3], ad, b1.y);
                }
                aP += 1; bP += STR;
            }
        }

        // ---- scale by fp16-roundtripped norm, store coalesced ----
        #pragma unroll
        for (int i = 0; i < 8; ++i) {
            int r = tr * 4 + ((i < 4) ? i : (i + 60));
            float nq = sNq[r];
            float2 p0 = unpack2(acc[i][0]);
            float2 p1 = unpack2(acc[i][1]);
            float2 p2 = unpack2(acc[i][2]);
            float2 p3 = unpack2(acc[i][3]);
            float4 o0 = make_float4(p0.x * nq, p0.y * nq, p1.x * nq, p1.y * nq);
            float4 o1 = make_float4(p2.x * nq, p2.y * nq, p3.x * nq, p3.y * nq);
            *reinterpret_cast<float4*>(&gout[r * 128 + tc * 4])      = o0;
            *reinterpret_cast<float4*>(&gout[r * 128 + tc * 4 + 64]) = o1;
        }
    }
}

extern "C" void kernel_launch(void* const* d_in, const int* in_sizes, int n_in,
                              void* d_out, int out_size) {
    const float* x   = (const float*)d_in[0];
    const float* Pi  = (const float*)d_in[1];
    const float* cen = (const float*)d_in[2];
    const float* bnd = (const float*)d_in[3];
    float* out = (float*)d_out;

    int N = in_sizes[0] / 128;     // number of rows
    int n_tiles = N / 128;         // 2048 for the given shape

    int nsm = 148;
    cudaDeviceGetAttribute(&nsm, cudaDevAttrMultiProcessorCount, 0);
    if (nsm <= 0) nsm = 148;

    size_t smem_bytes = (size_t)(3 * 128 * STR + 128 + 128 + 16 + 16) * sizeof(float);
    cudaFuncSetAttribute(tq_kernel, cudaFuncAttributeMaxDynamicSharedMemorySize, (int)smem_bytes);

    tq_kernel<<<nsm, THREADS, smem_bytes>>>(x, Pi, cen, bnd, out, n_tiles);
}

// round 3
// speedup vs baseline: 1.0192x; 1.0192x over previous
#include <cuda_runtime.h>
#include <cuda_fp16.h>

#define STR 132           // padded shared row stride (floats); 528B rows, 16B-aligned
#define THREADS 512

// ---------------- f32x2 helpers (sm_103a packed fp32, 2x FFMA throughput) ----------------
__device__ __forceinline__ unsigned long long dup_f32x2(float a) {
    unsigned long long r;
    unsigned int ai = __float_as_uint(a);
    asm("mov.b64 %0, {%1, %1};" : "=l"(r) : "r"(ai));
    return r;
}
__device__ __forceinline__ void fma2(unsigned long long &acc, unsigned long long a, unsigned long long b) {
    asm("fma.rn.f32x2 %0, %1, %2, %0;" : "+l"(acc) : "l"(a), "l"(b));
}
__device__ __forceinline__ float2 unpack2(unsigned long long v) {
    unsigned int lo, hi;
    asm("mov.b64 {%0, %1}, %2;" : "=r"(lo), "=r"(hi) : "l"(v));
    return make_float2(__uint_as_float(lo), __uint_as_float(hi));
}

// Lloyd-Max bucketize (matches jnp.searchsorted side='left' over interior boundaries)
__device__ __forceinline__ float quantize1(float v, const float* __restrict__ sB,
                                           const float* __restrict__ sC) {
    int idx = (v > sB[8]) ? 8 : 0;
    idx += (v > sB[idx + 4]) ? 4 : 0;
    idx += (v > sB[idx + 2]) ? 2 : 0;
    idx += (v > sB[idx + 1]) ? 1 : 0;
    return sC[idx];
}

__global__ __launch_bounds__(THREADS, 1)
void tq_kernel(const float* __restrict__ x, const float* __restrict__ Pi,
               const float* __restrict__ cen, const float* __restrict__ bnd,
               float* __restrict__ out, int n_tiles)
{
    extern __shared__ float smem[];
    float* sPi  = smem;                  // [128][STR] Pi[j][k] row-major
    float* sPiT = sPi  + 128 * STR;      // [128][STR] PiT[k][j]
    float* sX   = sPiT + 128 * STR;      // [128][STR] x tile; reused as values tile
    float* sRn  = sX   + 128 * STR;      // [128] 1/(norm+1e-8)
    float* sNq  = sRn  + 128;            // [128] fp16-roundtripped norm
    float* sB   = sNq  + 128;            // [16] boundaries (1..15 interior)
    float* sC   = sB   + 16;             // [16] centroids

    const int tid = threadIdx.x;
    const int tc  = tid & 15;            // col group: cols tc*4 .. +3 and +64
    const int tr  = tid >> 4;            // row group: rows tr*4 .. tr*4+3  (tr in 0..31)

    // ---- stage Pi and PiT once per block ----
    #pragma unroll
    for (int it = 0; it < 8; ++it) {
        int idx = it * THREADS + tid;    // 4096 float4 total
        int r = idx >> 5, c4 = idx & 31;
        float4 v = reinterpret_cast<const float4*>(Pi)[idx];
        *reinterpret_cast<float4*>(&sPi[r * STR + c4 * 4]) = v;
        sPiT[(c4 * 4 + 0) * STR + r] = v.x;
        sPiT[(c4 * 4 + 1) * STR + r] = v.y;
        sPiT[(c4 * 4 + 2) * STR + r] = v.z;
        sPiT[(c4 * 4 + 3) * STR + r] = v.w;
    }
    if (tid < 16) sC[tid] = cen[tid];
    if (tid < 16) sB[tid] = bnd[tid];
    __syncthreads();

    for (int tile = blockIdx.x; tile < n_tiles; tile += gridDim.x) {
        const float* gx   = x   + (size_t)tile * 128 * 128;
        float*       gout = out + (size_t)tile * 128 * 128;

        __syncthreads();  // previous tile's readers of sX are done

        // ---- stage x tile ----
        #pragma unroll
        for (int it = 0; it < 8; ++it) {
            int idx = it * THREADS + tid;
            int r = idx >> 5, c4 = idx & 31;
            float4 v = reinterpret_cast<const float4*>(gx)[idx];
            *reinterpret_cast<float4*>(&sX[r * STR + c4 * 4]) = v;
        }
        __syncthreads();

        // ---- per-row norms (threads 0..127) ----
        if (tid < 128) {
            const float* row = &sX[tid * STR];
            float s = 0.f;
            #pragma unroll
            for (int k = 0; k < 128; k += 4) {
                float4 v = *reinterpret_cast<const float4*>(&row[k]);
                s += v.x * v.x + v.y * v.y + v.z * v.z + v.w * v.w;
            }
            float nrm = sqrtf(s);
            sRn[tid] = 1.0f / (nrm + 1e-8f);
            sNq[tid] = __half2float(__float2half_rn(nrm));
        }
        __syncthreads();

        // ---- GEMM 1: rot[r][j] = sum_k x[r][k] * Pi[j][k] ----
        unsigned long long acc[4][4];
        #pragma unroll
        for (int i = 0; i < 4; ++i)
            #pragma unroll
            for (int j = 0; j < 4; ++j) acc[i][j] = 0ull;

        {
            const float* aP = sX   + (tr * 4) * STR;  // rows tr*4+i, col k
            const float* bP = sPiT + tc * 4;          // row k, cols tc*4.. and +64
            #pragma unroll 4
            for (int k = 0; k < 128; ++k) {
                ulonglong2 b0 = *reinterpret_cast<const ulonglong2*>(bP);
                ulonglong2 b1 = *reinterpret_cast<const ulonglong2*>(bP + 64);
                #pragma unroll
                for (int i = 0; i < 4; ++i) {
                    unsigned long long ad = dup_f32x2(aP[i * STR]);
                    fma2(acc[i][0], ad, b0.x);
                    fma2(acc[i][1], ad, b0.y);
                    fma2(acc[i][2], ad, b1.x);
                    fma2(acc[i][3], ad, b1.y);
                }
                aP += 1; bP += STR;
            }
        }

        __syncthreads();  // all reads of x tile done before overwrite

        // ---- quantize (fused) -> values tile ----
        #pragma unroll
        for (int i = 0; i < 4; ++i) {
            int r = tr * 4 + i;
            float rnv = sRn[r];
            float q[8];
            #pragma unroll
            for (int jp = 0; jp < 4; ++jp) {
                float2 p = unpack2(acc[i][jp]);
                q[2 * jp + 0] = quantize1(p.x * rnv, sB, sC);
                q[2 * jp + 1] = quantize1(p.y * rnv, sB, sC);
            }
            *reinterpret_cast<float4*>(&sX[r * STR + tc * 4])      = make_float4(q[0], q[1], q[2], q[3]);
            *reinterpret_cast<float4*>(&sX[r * STR + tc * 4 + 64]) = make_float4(q[4], q[5], q[6], q[7]);
        }
        __syncthreads();

        // ---- GEMM 2: recon[r][k] = sum_j values[r][j] * Pi[j][k] ----
        #pragma unroll
        for (int i = 0; i < 4; ++i)
            #pragma unroll
            for (int j = 0; j < 4; ++j) acc[i][j] = 0ull;

        {
            const float* aP = sX  + (tr * 4) * STR;   // values row, col j
            const float* bP = sPi + tc * 4;           // Pi row j, cols tc*4.. and +64
            #pragma unroll 4
            for (int j = 0; j < 128; ++j) {
                ulonglong2 b0 = *reinterpret_cast<const ulonglong2*>(bP);
                ulonglong2 b1 = *reinterpret_cast<const ulonglong2*>(bP + 64);
                #pragma unroll
                for (int i = 0; i < 4; ++i) {
                    unsigned long long ad = dup_f32x2(aP[i * STR]);
                    fma2(acc[i][0], ad, b0.x);
                    fma2(acc[i][1], ad, b0.y);
                    fma2(acc[i][2], ad, b1.x);
                    fma2(acc[i][3], ad, b1.y);
                }
                aP += 1; bP += STR;
            }
        }

        // ---- scale by fp16-roundtripped norm, store coalesced ----
        #pragma unroll
        for (int i = 0; i < 4; ++i) {
            int r = tr * 4 + i;
            float nq = sNq[r];
            float2 p0 = unpack2(acc[i][0]);
            float2 p1 = unpack2(acc[i][1]);
            float2 p2 = unpack2(acc[i][2]);
            float2 p3 = unpack2(acc[i][3]);
            float4 o0 = make_float4(p0.x * nq, p0.y * nq, p1.x * nq, p1.y * nq);
            float4 o1 = make_float4(p2.x * nq, p2.y * nq, p3.x * nq, p3.y * nq);
            *reinterpret_cast<float4*>(&gout[r * 128 + tc * 4])      = o0;
            *reinterpret_cast<float4*>(&gout[r * 128 + tc * 4 + 64]) = o1;
        }
    }
}

extern "C" void kernel_launch(void* const* d_in, const int* in_sizes, int n_in,
                              void* d_out, int out_size) {
    const float* x   = (const float*)d_in[0];
    const float* Pi  = (const float*)d_in[1];
    const float* cen = (const float*)d_in[2];
    const float* bnd = (const float*)d_in[3];
    float* out = (float*)d_out;

    int N = in_sizes[0] / 128;
    int n_tiles = N / 128;

    int nsm = 148;
    cudaDeviceGetAttribute(&nsm, cudaDevAttrMultiProcessorCount, 0);
    if (nsm <= 0) nsm = 148;

    size_t smem_bytes = (size_t)(3 * 128 * STR + 128 + 128 + 16 + 16) * sizeof(float);
    cudaFuncSetAttribute(tq_kernel, cudaFuncAttributeMaxDynamicSharedMemorySize, (int)smem_bytes);

    tq_kernel<<<nsm, THREADS, smem_bytes>>>(x, Pi, cen, bnd, out, n_tiles);
}

// round 5
// speedup vs baseline: 1.0837x; 1.0632x over previous
#include <cuda_runtime.h>
#include <cuda_fp16.h>

#define STR 132           // padded shared row stride (floats)
#define THREADS 512

// ---------------- f32x2 helpers (sm_103a packed fp32 FFMA2) ----------------
__device__ __forceinline__ unsigned long long dup_f32x2(float a) {
    unsigned long long r;
    unsigned int ai = __float_as_uint(a);
    asm("mov.b64 %0, {%1, %1};" : "=l"(r) : "r"(ai));
    return r;
}
__device__ __forceinline__ void fma2(unsigned long long &acc, unsigned long long a, unsigned long long b) {
    asm("fma.rn.f32x2 %0, %1, %2, %0;" : "+l"(acc) : "l"(a), "l"(b));
}
__device__ __forceinline__ float2 unpack2(unsigned long long v) {
    unsigned int lo, hi;
    asm("mov.b64 {%0, %1}, %2;" : "=r"(lo), "=r"(hi) : "l"(v));
    return make_float2(__uint_as_float(lo), __uint_as_float(hi));
}

// Lloyd-Max bucketize (matches jnp.searchsorted side='left' over interior boundaries)
__device__ __forceinline__ float quantize1(float v, const float* __restrict__ sB,
                                           const float* __restrict__ sC) {
    int idx = (v > sB[8]) ? 8 : 0;
    idx += (v > sB[idx + 4]) ? 4 : 0;
    idx += (v > sB[idx + 2]) ? 2 : 0;
    idx += (v > sB[idx + 1]) ? 1 : 0;
    return sC[idx];
}

__global__ __launch_bounds__(THREADS, 1)
void tq_kernel(const float* __restrict__ x, const float* __restrict__ Pi,
               const float* __restrict__ cen, const float* __restrict__ bnd,
               float* __restrict__ out, int n_tiles)
{
    extern __shared__ float smem[];
    float* sPi  = smem;                  // [128][STR] Pi[j][k] row-major
    float* sPiT = sPi  + 128 * STR;      // [128][STR] PiT[k][j]
    float* sX   = sPiT + 128 * STR;      // [128][STR] x tile; reused as values tile
    float* sRn  = sX   + 128 * STR;      // [128] 1/(norm+1e-8)
    float* sNq  = sRn  + 128;            // [128] fp16-roundtripped norm
    float* sB   = sNq  + 128;            // [16] boundaries (1..15 interior)
    float* sC   = sB   + 16;             // [16] centroids

    const int tid  = threadIdx.x;
    const int w    = tid >> 5;           // warp id 0..15 -> rows w*8 .. w*8+7
    const int lane = tid & 31;           // lane -> cols lane*4 .. lane*4+3
    const int r0   = w * 8;
    const int c0   = lane * 4;

    // ---- stage Pi and PiT once per block ----
    #pragma unroll
    for (int it = 0; it < 8; ++it) {
        int idx = it * THREADS + tid;    // 4096 float4 total
        int r = idx >> 5, c4 = idx & 31;
        float4 v = reinterpret_cast<const float4*>(Pi)[idx];
        *reinterpret_cast<float4*>(&sPi[r * STR + c4 * 4]) = v;
        sPiT[(c4 * 4 + 0) * STR + r] = v.x;
        sPiT[(c4 * 4 + 1) * STR + r] = v.y;
        sPiT[(c4 * 4 + 2) * STR + r] = v.z;
        sPiT[(c4 * 4 + 3) * STR + r] = v.w;
    }
    if (tid < 16) sC[tid] = cen[tid];
    if (tid < 16) sB[tid] = bnd[tid];
    __syncthreads();

    for (int tile = blockIdx.x; tile < n_tiles; tile += gridDim.x) {
        const float* gx   = x   + (size_t)tile * 128 * 128;
        float*       gout = out + (size_t)tile * 128 * 128;

        __syncthreads();  // previous tile's readers of sX are done

        // ---- stage x tile ----
        #pragma unroll
        for (int it = 0; it < 8; ++it) {
            int idx = it * THREADS + tid;
            int r = idx >> 5, c4 = idx & 31;
            float4 v = reinterpret_cast<const float4*>(gx)[idx];
            *reinterpret_cast<float4*>(&sX[r * STR + c4 * 4]) = v;
        }
        __syncthreads();

        // ---- per-row norms (threads 0..127) ----
        if (tid < 128) {
            const float* row = &sX[tid * STR];
            float s = 0.f;
            #pragma unroll
            for (int k = 0; k < 128; k += 4) {
                float4 v = *reinterpret_cast<const float4*>(&row[k]);
                s += v.x * v.x + v.y * v.y + v.z * v.z + v.w * v.w;
            }
            float nrm = sqrtf(s);
            sRn[tid] = 1.0f / (nrm + 1e-8f);
            sNq[tid] = __half2float(__float2half_rn(nrm));
        }
        __syncthreads();

        // ---- GEMM 1: rot[r][j] = sum_k x[r][k] * Pi[j][k]
        //      thread: rows r0..r0+7, cols c0..c0+3 (warp spans all 128 cols) ----
        unsigned long long acc[8][2];
        #pragma unroll
        for (int i = 0; i < 8; ++i) { acc[i][0] = 0ull; acc[i][1] = 0ull; }

        #pragma unroll 8
        for (int kb = 0; kb < 32; ++kb) {
            float4 av[8];
            #pragma unroll
            for (int i = 0; i < 8; ++i)
                av[i] = *reinterpret_cast<const float4*>(&sX[(r0 + i) * STR + kb * 4]);
            #pragma unroll
            for (int t = 0; t < 4; ++t) {
                ulonglong2 b = *reinterpret_cast<const ulonglong2*>(&sPiT[(kb * 4 + t) * STR + c0]);
                #pragma unroll
                for (int i = 0; i < 8; ++i) {
                    float a = (t == 0) ? av[i].x : (t == 1) ? av[i].y : (t == 2) ? av[i].z : av[i].w;
                    unsigned long long ad = dup_f32x2(a);
                    fma2(acc[i][0], ad, b.x);
                    fma2(acc[i][1], ad, b.y);
                }
            }
        }

        __syncthreads();  // all reads of x tile done before overwrite

        // ---- quantize (fused) -> values tile ----
        #pragma unroll
        for (int i = 0; i < 8; ++i) {
            int r = r0 + i;
            float rnv = sRn[r];
            float2 p0 = unpack2(acc[i][0]);
            float2 p1 = unpack2(acc[i][1]);
            float4 q;
            q.x = quantize1(p0.x * rnv, sB, sC);
            q.y = quantize1(p0.y * rnv, sB, sC);
            q.z = quantize1(p1.x * rnv, sB, sC);
            q.w = quantize1(p1.y * rnv, sB, sC);
            *reinterpret_cast<float4*>(&sX[r * STR + c0]) = q;
        }
        __syncthreads();

        // ---- GEMM 2: recon[r][k] = sum_j values[r][j] * Pi[j][k]
        //      thread: rows r0..r0+7, cols (k) c0..c0+3 ----
        #pragma unroll
        for (int i = 0; i < 8; ++i) { acc[i][0] = 0ull; acc[i][1] = 0ull; }

        #pragma unroll 8
        for (int jb = 0; jb < 32; ++jb) {
            float4 av[8];
            #pragma unroll
            for (int i = 0; i < 8; ++i)
                av[i] = *reinterpret_cast<const float4*>(&sX[(r0 + i) * STR + jb * 4]);
            #pragma unroll
            for (int t = 0; t < 4; ++t) {
                ulonglong2 b = *reinterpret_cast<const ulonglong2*>(&sPi[(jb * 4 + t) * STR + c0]);
                #pragma unroll
                for (int i = 0; i < 8; ++i) {
                    float a = (t == 0) ? av[i].x : (t == 1) ? av[i].y : (t == 2) ? av[i].z : av[i].w;
                    unsigned long long ad = dup_f32x2(a);
                    fma2(acc[i][0], ad, b.x);
                    fma2(acc[i][1], ad, b.y);
                }
            }
        }

        // ---- scale by fp16-roundtripped norm, store coalesced ----
        #pragma unroll
        for (int i = 0; i < 8; ++i) {
            int r = r0 + i;
            float nq = sNq[r];
            float2 p0 = unpack2(acc[i][0]);
            float2 p1 = unpack2(acc[i][1]);
            float4 o = make_float4(p0.x * nq, p0.y * nq, p1.x * nq, p1.y * nq);
            *reinterpret_cast<float4*>(&gout[r * 128 + c0]) = o;
        }
    }
}

extern "C" void kernel_launch(void* const* d_in, const int* in_sizes, int n_in,
                              void* d_out, int out_size) {
    const float* x   = (const float*)d_in[0];
    const float* Pi  = (const float*)d_in[1];
    const float* cen = (const float*)d_in[2];
    const float* bnd = (const float*)d_in[3];
    float* out = (float*)d_out;

    int N = in_sizes[0] / 128;
    int n_tiles = N / 128;

    int nsm = 148;
    cudaDeviceGetAttribute(&nsm, cudaDevAttrMultiProcessorCount, 0);
    if (nsm <= 0) nsm = 148;

    size_t smem_bytes = (size_t)(3 * 128 * STR + 128 + 128 + 16 + 16) * sizeof(float);
    cudaFuncSetAttribute(tq_kernel, cudaFuncAttributeMaxDynamicSharedMemorySize, (int)smem_bytes);

    tq_kernel<<<nsm, THREADS, smem_bytes>>>(x, Pi, cen, bnd, out, n_tiles);
}